// round 14
// baseline (speedup 1.0000x reference)
#include <cuda_runtime.h>
#include <cuda_fp16.h>
#include <cstdint>

#define EMB   1024
#define T_SEQ 2048
#define BATCH 2
#define HEADS 16
#define HD    64
#define MROWS (BATCH * T_SEQ)   /* 4096 */
#define FF    (4 * EMB)         /* 4096 */

// -------------------- scratch (static device globals) ----------------------
__device__ __half g_h  [MROWS * EMB];
__device__ __half g_qkv[3 * MROWS * EMB];
__device__ __half g_at [MROWS * EMB];
__device__ float  g_x2 [MROWS * EMB];
__device__ __half g_h2 [MROWS * EMB];
__device__ __half g_u  [MROWS * FF];
__device__ __half g_wqkv[3 * EMB * EMB];
__device__ __half g_wo  [EMB * EMB];
__device__ __half g_w1  [EMB * FF];
__device__ __half g_w2  [FF * EMB];

// -------------------- helpers ----------------------------------------------
__device__ __forceinline__ uint32_t smem_u32(const void* p) {
    uint32_t a;
    asm("{ .reg .u64 t; cvta.to.shared.u64 t, %1; cvt.u32.u64 %0, t; }" : "=r"(a) : "l"(p));
    return a;
}
__device__ __forceinline__ void cp16(uint32_t dst, const void* src) {
    asm volatile("cp.async.cg.shared.global [%0], [%1], 16;" :: "r"(dst), "l"(src) : "memory");
}
__device__ __forceinline__ void cp_commit() {
    asm volatile("cp.async.commit_group;" ::: "memory");
}
__device__ __forceinline__ void ldsm4(uint32_t* r, uint32_t addr) {
    asm volatile("ldmatrix.sync.aligned.m8n8.x4.shared.b16 {%0,%1,%2,%3}, [%4];"
                 : "=r"(r[0]), "=r"(r[1]), "=r"(r[2]), "=r"(r[3]) : "r"(addr));
}
__device__ __forceinline__ void ldsm4t(uint32_t* r, uint32_t addr) {
    asm volatile("ldmatrix.sync.aligned.m8n8.x4.trans.shared.b16 {%0,%1,%2,%3}, [%4];"
                 : "=r"(r[0]), "=r"(r[1]), "=r"(r[2]), "=r"(r[3]) : "r"(addr));
}
__device__ __forceinline__ void mma16816(float* d, const uint32_t* a, const uint32_t* b) {
    asm volatile(
        "mma.sync.aligned.m16n8k16.row.col.f32.f16.f16.f32 "
        "{%0,%1,%2,%3}, {%4,%5,%6,%7}, {%8,%9}, {%0,%1,%2,%3};"
        : "+f"(d[0]), "+f"(d[1]), "+f"(d[2]), "+f"(d[3])
        : "r"(a[0]), "r"(a[1]), "r"(a[2]), "r"(a[3]), "r"(b[0]), "r"(b[1]));
}
__device__ __forceinline__ void mma16816h(uint32_t* d, const uint32_t* a, const uint32_t* b) {
    asm volatile(
        "mma.sync.aligned.m16n8k16.row.col.f16.f16.f16.f16 "
        "{%0,%1}, {%2,%3,%4,%5}, {%6,%7}, {%0,%1};"
        : "+r"(d[0]), "+r"(d[1])
        : "r"(a[0]), "r"(a[1]), "r"(a[2]), "r"(a[3]), "r"(b[0]), "r"(b[1]));
}

// -------------------- LayerNorm row (device fn) ------------------------------
__device__ __forceinline__ void ln_row(
    const float* __restrict__ X, const float* __restrict__ gam,
    const float* __restrict__ bet, __half* __restrict__ Y, int row,
    float* sh_s, float* sh_ss, float* sh_mr)
{
    const int tid = threadIdx.x;
    const float4 v = *reinterpret_cast<const float4*>(X + (size_t)row * EMB + tid * 4);
    float s  = v.x + v.y + v.z + v.w;
    float ss = v.x * v.x + v.y * v.y + v.z * v.z + v.w * v.w;
#pragma unroll
    for (int o = 16; o > 0; o >>= 1) {
        s  += __shfl_xor_sync(0xffffffffu, s,  o);
        ss += __shfl_xor_sync(0xffffffffu, ss, o);
    }
    const int wid = tid >> 5, lid = tid & 31;
    if (lid == 0) { sh_s[wid] = s; sh_ss[wid] = ss; }
    __syncthreads();
    if (tid == 0) {
        float ts = 0.f, tss = 0.f;
#pragma unroll
        for (int i = 0; i < 8; i++) { ts += sh_s[i]; tss += sh_ss[i]; }
        const float mean = ts * (1.0f / EMB);
        const float var  = tss * (1.0f / EMB) - mean * mean;
        sh_mr[0] = mean;
        sh_mr[1] = rsqrtf(var + 1e-5f);
    }
    __syncthreads();
    const float mean = sh_mr[0], r = sh_mr[1];
    const float4 g4 = *reinterpret_cast<const float4*>(gam + tid * 4);
    const float4 b4 = *reinterpret_cast<const float4*>(bet + tid * 4);
    const size_t o = (size_t)row * EMB + tid * 4;
    *reinterpret_cast<__half2*>(Y + o) = __floats2half2_rn(
        (v.x - mean) * r * g4.x + b4.x, (v.y - mean) * r * g4.y + b4.y);
    *reinterpret_cast<__half2*>(Y + o + 2) = __floats2half2_rn(
        (v.z - mean) * r * g4.z + b4.z, (v.w - mean) * r * g4.w + b4.w);
}

__global__ void __launch_bounds__(256) ln_h_kernel(
    const float* __restrict__ X, const float* __restrict__ gam,
    const float* __restrict__ bet, __half* __restrict__ Y)
{
    __shared__ float sh_s[8], sh_ss[8], sh_mr[2];
    ln_row(X, gam, bet, Y, blockIdx.x, sh_s, sh_ss, sh_mr);
}

// -------------------- fused prep: weight transposes (64x64 tiles) + LN1 ------
__global__ void __launch_bounds__(256) prep_kernel(
    const float* __restrict__ wq, const float* __restrict__ wk,
    const float* __restrict__ wv, const float* __restrict__ wo,
    const float* __restrict__ w1, const float* __restrict__ w2,
    const float* __restrict__ x,  const float* __restrict__ g1,
    const float* __restrict__ b1,
    __half* __restrict__ wqkvh, __half* __restrict__ woh,
    __half* __restrict__ w1h,   __half* __restrict__ w2h,
    __half* __restrict__ hout)
{
    __shared__ float tile[64][68];
    const int bid = blockIdx.x;
    const int tid = threadIdx.x;
    if (bid >= 3072) {
        float* sh_s  = &tile[0][0];
        float* sh_ss = &tile[1][0];
        float* sh_mr = &tile[2][0];
        ln_row(x, g1, b1, hout, bid - 3072, sh_s, sh_ss, sh_mr);
        return;
    }
    const float* W; __half* D; int K, N, MODE, idx;
    if (bid < 768) {
        const int w = bid >> 8; idx = bid & 255;
        W = (w == 0) ? wq : (w == 1) ? wk : wv;
        D = wqkvh + (size_t)w * EMB * EMB; K = EMB; N = EMB; MODE = 1;
    } else if (bid < 1024) {
        idx = bid - 768;  W = wo; D = woh; K = EMB; N = EMB; MODE = 0;
    } else if (bid < 2048) {
        idx = bid - 1024; W = w1; D = w1h; K = EMB; N = FF;  MODE = 0;
    } else {
        idx = bid - 2048; W = w2; D = w2h; K = FF;  N = EMB; MODE = 0;
    }
    const int nblk = N >> 6;
    const int n0 = (idx % nblk) * 64, k0 = (idx / nblk) * 64;

    const int lr = tid >> 4, lc = (tid & 15) * 4;
#pragma unroll
    for (int s = 0; s < 4; s++) {
        const int k = k0 + lr + s * 16;
        size_t base;
        if (MODE == 0) base = (size_t)k * N + n0 + lc;
        else           base = (((size_t)(n0 >> 6) * K + k) << 6) + lc;
        *reinterpret_cast<float4*>(&tile[lr + s * 16][lc]) =
            *reinterpret_cast<const float4*>(W + base);
    }
    __syncthreads();

    const int n = tid & 63;
#pragma unroll
    for (int g = 0; g < 2; g++) {
        const int kg = (tid >> 6) + g * 4;
        const int k = kg * 8;
        __half2 h4[4];
#pragma unroll
        for (int j = 0; j < 4; j++)
            h4[j] = __floats2half2_rn(tile[k + 2 * j][n], tile[k + 2 * j + 1][n]);
        *reinterpret_cast<uint4*>(D + (size_t)(n0 + n) * K + k0 + k) =
            *reinterpret_cast<uint4*>(h4);
    }
}

// -------------------- mma.sync fp16 GEMM: CTA 128x256, 512 thr, BK=64, 3-stage
// FACC=1: fp16 accumulators (2 regs per 16x8 tile). FACC=0: fp32.
#define RB    144                  /* 64 halfs + 16B pad */
#define ASTG  (128 * RB)           /* 18432 */
#define BSTG  (256 * RB)           /* 36864 */
#define STGB  (ASTG + BSTG)        /* 55296 */
#define NSTG  3
#define GSMEM_BYTES (NSTG * STGB)  /* 165888 */

template <int EPI, int FACC>
__global__ void __launch_bounds__(512, 1) mma_gemm(
    const __half* __restrict__ A, const __half* __restrict__ B,
    float* __restrict__ Cf, __half* __restrict__ Chp,
    const float* __restrict__ bias, const float* __restrict__ res,
    int M, int N, int K)
{
    extern __shared__ char smem[];
    const uint32_t sbase = smem_u32(smem);
    const int tid  = threadIdx.x;
    const int wid  = tid >> 5, lane = tid & 31;
    const int m0   = blockIdx.y * 128, n0 = blockIdx.x * 256;
    const int wm   = wid & 3;
    const int wn   = wid >> 2;

    const int arow_g = tid >> 2, aseg = tid & 3;
    const int brow_g = tid >> 1, bseg = tid & 1;
    const __half* gA = A + (size_t)(m0 + arow_g) * K + aseg * 16;
    const __half* gB = B + (size_t)(n0 + brow_g) * K + bseg * 32;
    const uint32_t sAw = sbase + arow_g * RB + aseg * 32;
    const uint32_t sBw = sbase + ASTG + brow_g * RB + bseg * 64;

    float    acc [2][8][4];
    uint32_t hacc[2][8][2];
#pragma unroll
    for (int i = 0; i < 2; i++)
#pragma unroll
        for (int j = 0; j < 8; j++) {
            if (FACC) { hacc[i][j][0] = 0u; hacc[i][j][1] = 0u; }
            else {
#pragma unroll
                for (int t = 0; t < 4; t++) acc[i][j][t] = 0.f;
            }
        }

    const int NC = K >> 6;

    const uint32_t aoff = (uint32_t)(wm * 32 + (lane & 15)) * RB + (lane >> 4) * 16;
    const uint32_t boff = (uint32_t)(wn * 64 + (lane & 7) + ((lane >> 4) << 3)) * RB +
                          ((lane >> 3) & 1) * 16 + ASTG;

    // prologue: chunks 0,1 -> stages 0,1
#pragma unroll
    for (int s = 0; s < NSTG - 1; s++) {
        const int k0 = s * 64;
        const uint32_t off = s * STGB;
#pragma unroll
        for (int i = 0; i < 2; i++) cp16(sAw + off + i * 16, gA + k0 + i * 8);
#pragma unroll
        for (int i = 0; i < 4; i++) cp16(sBw + off + i * 16, gB + k0 + i * 8);
        cp_commit();
    }

    uint32_t af[2][2][4], bf[2][4][4];

    for (int c = 0; c < NC; c++) {
        asm volatile("cp.async.wait_group 1;" ::: "memory");
        __syncthreads();
        if (c + 2 < NC) {
            const int k0 = (c + 2) * 64;
            const uint32_t off = (uint32_t)((c + 2) % NSTG) * STGB;
#pragma unroll
            for (int i = 0; i < 2; i++) cp16(sAw + off + i * 16, gA + k0 + i * 8);
#pragma unroll
            for (int i = 0; i < 4; i++) cp16(sBw + off + i * 16, gB + k0 + i * 8);
        }
        cp_commit();

        const uint32_t sb = sbase + (uint32_t)(c % NSTG) * STGB;
#pragma unroll
        for (int mi = 0; mi < 2; mi++)
            ldsm4(af[0][mi], sb + aoff + mi * 16 * RB);
#pragma unroll
        for (int nt = 0; nt < 4; nt++)
            ldsm4(bf[0][nt], sb + boff + nt * 16 * RB);

#pragma unroll
        for (int ks = 0; ks < 4; ks++) {
            const int cur = ks & 1, nxt = cur ^ 1;
            if (ks < 3) {
                const uint32_t ko = (uint32_t)(ks + 1) * 32;
#pragma unroll
                for (int mi = 0; mi < 2; mi++)
                    ldsm4(af[nxt][mi], sb + aoff + mi * 16 * RB + ko);
#pragma unroll
                for (int nt = 0; nt < 4; nt++)
                    ldsm4(bf[nxt][nt], sb + boff + nt * 16 * RB + ko);
            }
#pragma unroll
            for (int mi = 0; mi < 2; mi++)
#pragma unroll
                for (int nj = 0; nj < 8; nj++) {
                    if (FACC)
                        mma16816h(hacc[mi][nj], af[cur][mi], &bf[cur][nj >> 1][(nj & 1) * 2]);
                    else
                        mma16816(acc[mi][nj], af[cur][mi], &bf[cur][nj >> 1][(nj & 1) * 2]);
                }
        }
    }

    // epilogue
    const int mrow = m0 + wm * 32 + (lane >> 2);
    const int ncol = n0 + wn * 64 + (lane & 3) * 2;
#pragma unroll
    for (int mi = 0; mi < 2; mi++)
#pragma unroll
        for (int nj = 0; nj < 8; nj++)
#pragma unroll
            for (int hf = 0; hf < 2; hf++) {
                const int m = mrow + mi * 16 + hf * 8;
                const int n = ncol + nj * 8;
                float v0, v1;
                if (FACC) {
                    const __half2 hv = *reinterpret_cast<__half2*>(&hacc[mi][nj][hf]);
                    const float2 fv = __half22float2(hv);
                    v0 = fv.x; v1 = fv.y;
                } else {
                    v0 = acc[mi][nj][hf * 2 + 0];
                    v1 = acc[mi][nj][hf * 2 + 1];
                }
                if (EPI == 0) {
                    const int mat = n >> 10, hh = (n >> 6) & 15, d = n & 63;
                    const int bb = m >> 11, t = m & 2047;
                    __half2* dst = reinterpret_cast<__half2*>(
                        Chp + (size_t)mat * (MROWS * EMB) +
                        (((size_t)(bb * HEADS + hh)) * T_SEQ + t) * HD + d);
                    if (FACC) *dst = *reinterpret_cast<__half2*>(&hacc[mi][nj][hf]);
                    else      *dst = __floats2half2_rn(v0, v1);
                } else if (EPI == 1) {
                    const size_t base = (size_t)m * N + n;
                    const float2 bs = *reinterpret_cast<const float2*>(bias + n);
                    const float2 rs = *reinterpret_cast<const float2*>(res + base);
                    *reinterpret_cast<float2*>(Cf + base) =
                        make_float2(v0 + bs.x + rs.x, v1 + bs.y + rs.y);
                } else {
                    const size_t base = (size_t)m * N + n;
                    const float2 bs = *reinterpret_cast<const float2*>(bias + n);
                    *reinterpret_cast<__half2*>(Chp + base) =
                        __floats2half2_rn(fmaxf(v0 + bs.x, 0.f), fmaxf(v1 + bs.y, 0.f));
                }
            }
}

// -------------------- tensor-core causal flash attention (fp16) -------------
#define KVROWB 144
#define QTILEB  (128 * KVROWB)
#define KVSTGB  (2 * 64 * KVROWB)
#define ATT_SMEM (QTILEB + 2 * KVSTGB)

__global__ void __launch_bounds__(256) attn_mma(
    const __half* __restrict__ Qg, const __half* __restrict__ Kg,
    const __half* __restrict__ Vg, __half* __restrict__ Og)
{
    extern __shared__ char sm[];
    const uint32_t sb = smem_u32(sm);
    const int tid = threadIdx.x, w = tid >> 5, lane = tid & 31;
    const int bh = blockIdx.y;
    const int tileix = (int)gridDim.x - 1 - (int)blockIdx.x;
    const int t0 = tileix * 128;
    const int nc = 2 * tileix + 2;

    const size_t bhbase = (size_t)bh * T_SEQ;

    {
        const int lrow = tid >> 1, lhalf = tid & 1;
        const __half* qs = Qg + (bhbase + t0 + lrow) * HD + lhalf * 32;
        const uint32_t qd = sb + lrow * KVROWB + lhalf * 64;
#pragma unroll
        for (int i = 0; i < 4; i++) cp16(qd + i * 16, qs + i * 8);
    }
    const int krow = tid >> 2, kseg = tid & 3;
    {
        const __half* ks = Kg + (bhbase + krow) * HD + kseg * 16;
        const __half* vs = Vg + (bhbase + krow) * HD + kseg * 16;
        const uint32_t kd = sb + QTILEB + krow * KVROWB + kseg * 32;
        cp16(kd,      ks);
        cp16(kd + 16, ks + 8);
        cp16(kd + 64 * KVROWB,      vs);
        cp16(kd + 64 * KVROWB + 16, vs + 8);
    }
    cp_commit();

    float o[8][4];
#pragma unroll
    for (int dn = 0; dn < 8; dn++)
#pragma unroll
        for (int t = 0; t < 4; t++) o[dn][t] = 0.f;
    float m1 = -1e30f, m2 = -1e30f, l1 = 0.f, l2 = 0.f;
    uint32_t qf[4][4];

    const int arow  = w * 16 + (lane & 15);
    const int akoff = (lane >> 4) * 8;
    const int brow  = (lane & 7) + ((lane >> 4) << 3);
    const int bkoff = ((lane >> 3) & 1) * 8;
    const int vrowo = (lane & 7) + 8 * ((lane >> 3) & 1);
    const int vcolo = 16 * (lane >> 4);
    const int rw = t0 + w * 16;

    for (int c = 0; c < nc; c++) {
        if (c + 1 < nc) {
            const int j0 = (c + 1) * 64;
            const __half* ks = Kg + (bhbase + j0 + krow) * HD + kseg * 16;
            const __half* vs = Vg + (bhbase + j0 + krow) * HD + kseg * 16;
            const uint32_t kd = sb + QTILEB + ((c + 1) & 1) * KVSTGB + krow * KVROWB + kseg * 32;
            cp16(kd,      ks);
            cp16(kd + 16, ks + 8);
            cp16(kd + 64 * KVROWB,      vs);
            cp16(kd + 64 * KVROWB + 16, vs + 8);
            cp_commit();
            asm volatile("cp.async.wait_group 1;" ::: "memory");
        } else {
            asm volatile("cp.async.wait_group 0;" ::: "memory");
        }
        __syncthreads();

        if (c == 0) {
#pragma unroll
            for (int ks = 0; ks < 4; ks++)
                ldsm4(qf[ks], sb + arow * KVROWB + (ks * 16 + akoff) * 2);
        }

        const bool active = (64 * c <= rw + 15);
        const bool diag   = active && (64 * c + 63 > rw);
        if (active) {
            const uint32_t kb = sb + QTILEB + (c & 1) * KVSTGB;
            const uint32_t vb = kb + 64 * KVROWB;

            float s[8][4];
#pragma unroll
            for (int nj = 0; nj < 8; nj++)
#pragma unroll
                for (int t = 0; t < 4; t++) s[nj][t] = 0.f;
#pragma unroll
            for (int ks = 0; ks < 4; ks++) {
                uint32_t bK[4][4];
#pragma unroll
                for (int nt = 0; nt < 4; nt++)
                    ldsm4(bK[nt], kb + (nt * 16 + brow) * KVROWB + (ks * 16 + bkoff) * 2);
#pragma unroll
                for (int nj = 0; nj < 8; nj++)
                    mma16816(s[nj], qf[ks], &bK[nj >> 1][(nj & 1) * 2]);
            }
            const float sc = 0.03125f;
            if (diag) {
                const int r1 = rw + (lane >> 2);
#pragma unroll
                for (int nj = 0; nj < 8; nj++) {
                    const int kvb = 64 * c + nj * 8 + 2 * (lane & 3);
                    s[nj][0] = (kvb     <= r1    ) ? s[nj][0] * sc : -1e30f;
                    s[nj][1] = (kvb + 1 <= r1    ) ? s[nj][1] * sc : -1e30f;
                    s[nj][2] = (kvb     <= r1 + 8) ? s[nj][2] * sc : -1e30f;
                    s[nj][3] = (kvb + 1 <= r1 + 8) ? s[nj][3] * sc : -1e30f;
                }
            } else {
#pragma unroll
                for (int nj = 0; nj < 8; nj++)
#pragma unroll
                    for (int t = 0; t < 4; t++) s[nj][t] *= sc;
            }
            float mx1 = -1e30f, mx2 = -1e30f;
#pragma unroll
            for (int nj = 0; nj < 8; nj++) {
                mx1 = fmaxf(mx1, fmaxf(s[nj][0], s[nj][1]));
                mx2 = fmaxf(mx2, fmaxf(s[nj][2], s[nj][3]));
            }
            mx1 = fmaxf(mx1, __shfl_xor_sync(0xffffffffu, mx1, 1));
            mx1 = fmaxf(mx1, __shfl_xor_sync(0xffffffffu, mx1, 2));
            mx2 = fmaxf(mx2, __shfl_xor_sync(0xffffffffu, mx2, 1));
            mx2 = fmaxf(mx2, __shfl_xor_sync(0xffffffffu, mx2, 2));
            const float nm1 = fmaxf(m1, mx1), nm2 = fmaxf(m2, mx2);
            const float cor1 = __expf(m1 - nm1), cor2 = __expf(m2 - nm2);

            float ps1 = 0.f, ps2 = 0.f;
            uint32_t pf[4][4];
#pragma unroll
            for (int kk = 0; kk < 4; kk++) {
#pragma unroll
                for (int hf = 0; hf < 2; hf++) {
                    const int nj = kk * 2 + hf;
                    const float p0 = __expf(s[nj][0] - nm1);
                    const float p1 = __expf(s[nj][1] - nm1);
                    const float p2 = __expf(s[nj][2] - nm2);
                    const float p3 = __expf(s[nj][3] - nm2);
                    ps1 += p0 + p1;
                    ps2 += p2 + p3;
                    __half2 lo = __floats2half2_rn(p0, p1);
                    __half2 hi = __floats2half2_rn(p2, p3);
                    pf[kk][hf * 2 + 0] = *reinterpret_cast<uint32_t*>(&lo);
                    pf[kk][hf * 2 + 1] = *reinterpret_cast<uint32_t*>(&hi);
                }
            }
            ps1 += __shfl_xor_sync(0xffffffffu, ps1, 1);
            ps1 += __shfl_xor_sync(0xffffffffu, ps1, 2);
            ps2 += __shfl_xor_sync(0xffffffffu, ps2, 1);
            ps2 += __shfl_xor_sync(0xffffffffu, ps2, 2);
            l1 = l1 * cor1 + ps1;
            l2 = l2 * cor2 + ps2;
#pragma unroll
            for (int dn = 0; dn < 8; dn++) {
                o[dn][0] *= cor1; o[dn][1] *= cor1;
                o[dn][2] *= cor2; o[dn][3] *= cor2;
            }
            m1 = nm1; m2 = nm2;

#pragma unroll
            for (int kk = 0; kk < 4; kk++) {
                uint32_t bV[4][4];
                const uint32_t vr = vb + (kk * 16 + vrowo) * KVROWB + vcolo;
#pragma unroll
                for (int d16 = 0; d16 < 4; d16++)
                    ldsm4t(bV[d16], vr + d16 * 32);
#pragma unroll
                for (int dn = 0; dn < 8; dn++)
                    mma16816(o[dn], pf[kk], &bV[dn >> 1][(dn & 1) * 2]);
            }
        }
        __syncthreads();
    }

    const int b = bh >> 4, h = bh & 15;
    const float i1 = 1.f / l1, i2 = 1.f / l2;
    const int r1 = rw + (lane >> 2);
    __half* o1 = Og + ((size_t)(b * T_SEQ) + r1) * EMB + h * HD + 2 * (lane & 3);
    __half* o2 = o1 + (size_t)8 * EMB;
#pragma unroll
    for (int dn = 0; dn < 8; dn++) {
        *reinterpret_cast<__half2*>(o1 + dn * 8) =
            __floats2half2_rn(o[dn][0] * i1, o[dn][1] * i1);
        *reinterpret_cast<__half2*>(o2 + dn * 8) =
            __floats2half2_rn(o[dn][2] * i2, o[dn][3] * i2);
    }
}

// -------------------- launch -------------------------------------------------
extern "C" void kernel_launch(void* const* d_in, const int* in_sizes, int n_in,
                              void* d_out, int out_size)
{
    const float* x   = (const float*)d_in[0];
    const float* wq  = (const float*)d_in[1];
    const float* wk  = (const float*)d_in[2];
    const float* wv  = (const float*)d_in[3];
    const float* wo  = (const float*)d_in[4];
    const float* bo  = (const float*)d_in[5];
    const float* g1  = (const float*)d_in[6];
    const float* b1  = (const float*)d_in[7];
    const float* g2  = (const float*)d_in[8];
    const float* b2  = (const float*)d_in[9];
    const float* w1  = (const float*)d_in[10];
    const float* bf1 = (const float*)d_in[11];
    const float* w2  = (const float*)d_in[12];
    const float* bf2 = (const float*)d_in[13];
    float* out = (float*)d_out;

    cudaFuncSetAttribute(mma_gemm<0,1>, cudaFuncAttributeMaxDynamicSharedMemorySize, GSMEM_BYTES);
    cudaFuncSetAttribute(mma_gemm<1,1>, cudaFuncAttributeMaxDynamicSharedMemorySize, GSMEM_BYTES);
    cudaFuncSetAttribute(mma_gemm<1,0>, cudaFuncAttributeMaxDynamicSharedMemorySize, GSMEM_BYTES);
    cudaFuncSetAttribute(mma_gemm<2,0>, cudaFuncAttributeMaxDynamicSharedMemorySize, GSMEM_BYTES);
    cudaFuncSetAttribute(attn_mma, cudaFuncAttributeMaxDynamicSharedMemorySize, ATT_SMEM);

    __half *h, *qkv, *at, *h2, *u, *wqkvh, *woh, *w1h, *w2h;
    float *x2;
    cudaGetSymbolAddress((void**)&h,     g_h);
    cudaGetSymbolAddress((void**)&qkv,   g_qkv);
    cudaGetSymbolAddress((void**)&at,    g_at);
    cudaGetSymbolAddress((void**)&x2,    g_x2);
    cudaGetSymbolAddress((void**)&h2,    g_h2);
    cudaGetSymbolAddress((void**)&u,     g_u);
    cudaGetSymbolAddress((void**)&wqkvh, g_wqkv);
    cudaGetSymbolAddress((void**)&woh,   g_wo);
    cudaGetSymbolAddress((void**)&w1h,   g_w1);
    cudaGetSymbolAddress((void**)&w2h,   g_w2);

    // 1: fused prep (weight transposes + LN1)
    prep_kernel<<<7168, 256>>>(wq, wk, wv, wo, w1, w2, x, g1, b1,
                               wqkvh, woh, w1h, w2h, h);
    // 2: fused QKV projection (fp16 accumulate) -> [3][B,H,T,HD] fp16
    mma_gemm<0,1><<<dim3(3 * EMB / 256, MROWS / 128), 512, GSMEM_BYTES>>>(
        h, wqkvh, nullptr, qkv, nullptr, nullptr, MROWS, 3 * EMB, EMB);
    // 3: tensor-core flash attention (Q-tile 128, big-first) -> fp16 [B,T,C]
    attn_mma<<<dim3(T_SEQ / 128, BATCH * HEADS), 256, ATT_SMEM>>>(
        qkv, qkv + MROWS * EMB, qkv + 2 * MROWS * EMB, at);
    // 4: out projection (fp16 accumulate) + bias + residual(x) -> x2 fp32
    mma_gemm<1,1><<<dim3(EMB / 256, MROWS / 128), 512, GSMEM_BYTES>>>(
        at, woh, x2, nullptr, bo, x, MROWS, EMB, EMB);
    // 5: LN2 -> fp16
    ln_h_kernel<<<MROWS, 256>>>(x2, g2, b2, h2);
    // 6: FFN1 (fp32 accumulate): relu(h2 @ w1 + bf1) -> fp16   (profiled launch)
    mma_gemm<2,0><<<dim3(FF / 256, MROWS / 128), 512, GSMEM_BYTES>>>(
        h2, w1h, nullptr, u, bf1, nullptr, MROWS, FF, EMB);
    // 7: FFN2 (fp32 accumulate): u @ w2 + bf2 + x2 -> out fp32
    mma_gemm<1,0><<<dim3(EMB / 256, MROWS / 128), 512, GSMEM_BYTES>>>(
        u, w2h, out, nullptr, bf2, x2, MROWS, EMB, FF);
}

// round 15
// speedup vs baseline: 1.0182x; 1.0182x over previous
#include <cuda_runtime.h>
#include <cuda_fp16.h>
#include <cstdint>

#define EMB   1024
#define T_SEQ 2048
#define BATCH 2
#define HEADS 16
#define HD    64
#define MROWS (BATCH * T_SEQ)   /* 4096 */
#define FF    (4 * EMB)         /* 4096 */

// -------------------- scratch (static device globals) ----------------------
__device__ __half g_h  [MROWS * EMB];
__device__ __half g_qkv[3 * MROWS * EMB];
__device__ __half g_at [MROWS * EMB];
__device__ float  g_x2 [MROWS * EMB];
__device__ __half g_h2 [MROWS * EMB];
__device__ __half g_u  [MROWS * FF];
__device__ __half g_wqkv[3 * EMB * EMB];
__device__ __half g_wo  [EMB * EMB];
__device__ __half g_w1  [EMB * FF];
__device__ __half g_w2  [FF * EMB];

// -------------------- helpers ----------------------------------------------
__device__ __forceinline__ uint32_t smem_u32(const void* p) {
    uint32_t a;
    asm("{ .reg .u64 t; cvta.to.shared.u64 t, %1; cvt.u32.u64 %0, t; }" : "=r"(a) : "l"(p));
    return a;
}
__device__ __forceinline__ void cp16(uint32_t dst, const void* src) {
    asm volatile("cp.async.cg.shared.global [%0], [%1], 16;" :: "r"(dst), "l"(src) : "memory");
}
__device__ __forceinline__ void cp_commit() {
    asm volatile("cp.async.commit_group;" ::: "memory");
}
__device__ __forceinline__ void ldsm4(uint32_t* r, uint32_t addr) {
    asm volatile("ldmatrix.sync.aligned.m8n8.x4.shared.b16 {%0,%1,%2,%3}, [%4];"
                 : "=r"(r[0]), "=r"(r[1]), "=r"(r[2]), "=r"(r[3]) : "r"(addr));
}
__device__ __forceinline__ void ldsm4t(uint32_t* r, uint32_t addr) {
    asm volatile("ldmatrix.sync.aligned.m8n8.x4.trans.shared.b16 {%0,%1,%2,%3}, [%4];"
                 : "=r"(r[0]), "=r"(r[1]), "=r"(r[2]), "=r"(r[3]) : "r"(addr));
}
__device__ __forceinline__ void mma16816(float* d, const uint32_t* a, const uint32_t* b) {
    asm volatile(
        "mma.sync.aligned.m16n8k16.row.col.f32.f16.f16.f32 "
        "{%0,%1,%2,%3}, {%4,%5,%6,%7}, {%8,%9}, {%0,%1,%2,%3};"
        : "+f"(d[0]), "+f"(d[1]), "+f"(d[2]), "+f"(d[3])
        : "r"(a[0]), "r"(a[1]), "r"(a[2]), "r"(a[3]), "r"(b[0]), "r"(b[1]));
}
__device__ __forceinline__ void mma16816h(uint32_t* d, const uint32_t* a, const uint32_t* b) {
    asm volatile(
        "mma.sync.aligned.m16n8k16.row.col.f16.f16.f16.f16 "
        "{%0,%1}, {%2,%3,%4,%5}, {%6,%7}, {%0,%1};"
        : "+r"(d[0]), "+r"(d[1])
        : "r"(a[0]), "r"(a[1]), "r"(a[2]), "r"(a[3]), "r"(b[0]), "r"(b[1]));
}

// -------------------- LayerNorm row (device fn) ------------------------------
__device__ __forceinline__ void ln_row(
    const float* __restrict__ X, const float* __restrict__ gam,
    const float* __restrict__ bet, __half* __restrict__ Y, int row,
    float* sh_s, float* sh_ss, float* sh_mr)
{
    const int tid = threadIdx.x;
    const float4 v = *reinterpret_cast<const float4*>(X + (size_t)row * EMB + tid * 4);
    float s  = v.x + v.y + v.z + v.w;
    float ss = v.x * v.x + v.y * v.y + v.z * v.z + v.w * v.w;
#pragma unroll
    for (int o = 16; o > 0; o >>= 1) {
        s  += __shfl_xor_sync(0xffffffffu, s,  o);
        ss += __shfl_xor_sync(0xffffffffu, ss, o);
    }
    const int wid = tid >> 5, lid = tid & 31;
    if (lid == 0) { sh_s[wid] = s; sh_ss[wid] = ss; }
    __syncthreads();
    if (tid == 0) {
        float ts = 0.f, tss = 0.f;
#pragma unroll
        for (int i = 0; i < 8; i++) { ts += sh_s[i]; tss += sh_ss[i]; }
        const float mean = ts * (1.0f / EMB);
        const float var  = tss * (1.0f / EMB) - mean * mean;
        sh_mr[0] = mean;
        sh_mr[1] = rsqrtf(var + 1e-5f);
    }
    __syncthreads();
    const float mean = sh_mr[0], r = sh_mr[1];
    const float4 g4 = *reinterpret_cast<const float4*>(gam + tid * 4);
    const float4 b4 = *reinterpret_cast<const float4*>(bet + tid * 4);
    const size_t o = (size_t)row * EMB + tid * 4;
    *reinterpret_cast<__half2*>(Y + o) = __floats2half2_rn(
        (v.x - mean) * r * g4.x + b4.x, (v.y - mean) * r * g4.y + b4.y);
    *reinterpret_cast<__half2*>(Y + o + 2) = __floats2half2_rn(
        (v.z - mean) * r * g4.z + b4.z, (v.w - mean) * r * g4.w + b4.w);
}

__global__ void __launch_bounds__(256) ln_h_kernel(
    const float* __restrict__ X, const float* __restrict__ gam,
    const float* __restrict__ bet, __half* __restrict__ Y)
{
    __shared__ float sh_s[8], sh_ss[8], sh_mr[2];
    ln_row(X, gam, bet, Y, blockIdx.x, sh_s, sh_ss, sh_mr);
}

// -------------------- fused prep: weight transposes (64x64 tiles) + LN1 ------
__global__ void __launch_bounds__(256) prep_kernel(
    const float* __restrict__ wq, const float* __restrict__ wk,
    const float* __restrict__ wv, const float* __restrict__ wo,
    const float* __restrict__ w1, const float* __restrict__ w2,
    const float* __restrict__ x,  const float* __restrict__ g1,
    const float* __restrict__ b1,
    __half* __restrict__ wqkvh, __half* __restrict__ woh,
    __half* __restrict__ w1h,   __half* __restrict__ w2h,
    __half* __restrict__ hout)
{
    __shared__ float tile[64][68];
    const int bid = blockIdx.x;
    const int tid = threadIdx.x;
    if (bid >= 3072) {
        float* sh_s  = &tile[0][0];
        float* sh_ss = &tile[1][0];
        float* sh_mr = &tile[2][0];
        ln_row(x, g1, b1, hout, bid - 3072, sh_s, sh_ss, sh_mr);
        return;
    }
    const float* W; __half* D; int K, N, MODE, idx;
    if (bid < 768) {
        const int w = bid >> 8; idx = bid & 255;
        W = (w == 0) ? wq : (w == 1) ? wk : wv;
        D = wqkvh + (size_t)w * EMB * EMB; K = EMB; N = EMB; MODE = 1;
    } else if (bid < 1024) {
        idx = bid - 768;  W = wo; D = woh; K = EMB; N = EMB; MODE = 0;
    } else if (bid < 2048) {
        idx = bid - 1024; W = w1; D = w1h; K = EMB; N = FF;  MODE = 0;
    } else {
        idx = bid - 2048; W = w2; D = w2h; K = FF;  N = EMB; MODE = 0;
    }
    const int nblk = N >> 6;
    const int n0 = (idx % nblk) * 64, k0 = (idx / nblk) * 64;

    const int lr = tid >> 4, lc = (tid & 15) * 4;
#pragma unroll
    for (int s = 0; s < 4; s++) {
        const int k = k0 + lr + s * 16;
        size_t base;
        if (MODE == 0) base = (size_t)k * N + n0 + lc;
        else           base = (((size_t)(n0 >> 6) * K + k) << 6) + lc;
        *reinterpret_cast<float4*>(&tile[lr + s * 16][lc]) =
            *reinterpret_cast<const float4*>(W + base);
    }
    __syncthreads();

    const int n = tid & 63;
#pragma unroll
    for (int g = 0; g < 2; g++) {
        const int kg = (tid >> 6) + g * 4;
        const int k = kg * 8;
        __half2 h4[4];
#pragma unroll
        for (int j = 0; j < 4; j++)
            h4[j] = __floats2half2_rn(tile[k + 2 * j][n], tile[k + 2 * j + 1][n]);
        *reinterpret_cast<uint4*>(D + (size_t)(n0 + n) * K + k0 + k) =
            *reinterpret_cast<uint4*>(h4);
    }
}

// -------------------- persistent mma.sync fp16 GEMM --------------------------
// CTA 128x256, 512 thr, BK=64, 3-stage; persistent tile loop with next-tile
// prologue issued before epilogue. FACC=1: fp16 accumulators; FACC=0: fp32.
#define RB    144                  /* 64 halfs + 16B pad */
#define ASTG  (128 * RB)           /* 18432 */
#define BSTG  (256 * RB)           /* 36864 */
#define STGB  (ASTG + BSTG)        /* 55296 */
#define NSTG  3
#define GSMEM_BYTES (NSTG * STGB)  /* 165888 */

template <int EPI, int FACC>
__global__ void __launch_bounds__(512, 1) mma_gemm(
    const __half* __restrict__ A, const __half* __restrict__ B,
    float* __restrict__ Cf, __half* __restrict__ Chp,
    const float* __restrict__ bias, const float* __restrict__ res,
    int M, int N, int K)
{
    extern __shared__ char smem[];
    const uint32_t sbase = smem_u32(smem);
    const int tid  = threadIdx.x;
    const int wid  = tid >> 5, lane = tid & 31;
    const int wm   = wid & 3;
    const int wn   = wid >> 2;

    const int arow_g = tid >> 2, aseg = tid & 3;
    const int brow_g = tid >> 1, bseg = tid & 1;
    const uint32_t sAw = sbase + arow_g * RB + aseg * 32;
    const uint32_t sBw = sbase + ASTG + brow_g * RB + bseg * 64;

    const uint32_t aoff = (uint32_t)(wm * 32 + (lane & 15)) * RB + (lane >> 4) * 16;
    const uint32_t boff = (uint32_t)(wn * 64 + (lane & 7) + ((lane >> 4) << 3)) * RB +
                          ((lane >> 3) & 1) * 16 + ASTG;

    const int NC  = K >> 6;
    const int ntn = N >> 8;
    const int ntiles = (M >> 7) * ntn;

    int t = blockIdx.x;
    int m0 = (t / ntn) << 7, n0 = (t % ntn) << 8;
    const __half* gA = A + (size_t)(m0 + arow_g) * K + aseg * 16;
    const __half* gB = B + (size_t)(n0 + brow_g) * K + bseg * 32;

    // prologue for first tile: chunks 0,1 -> stages 0,1
#pragma unroll
    for (int s = 0; s < NSTG - 1; s++) {
        const int k0 = s * 64;
        const uint32_t off = s * STGB;
#pragma unroll
        for (int i = 0; i < 2; i++) cp16(sAw + off + i * 16, gA + k0 + i * 8);
#pragma unroll
        for (int i = 0; i < 4; i++) cp16(sBw + off + i * 16, gB + k0 + i * 8);
        cp_commit();
    }

    float    acc [2][8][4];
    uint32_t hacc[2][8][2];
    uint32_t af[2][2][4], bf[2][4][4];

    while (true) {
#pragma unroll
        for (int i = 0; i < 2; i++)
#pragma unroll
            for (int j = 0; j < 8; j++) {
                if (FACC) { hacc[i][j][0] = 0u; hacc[i][j][1] = 0u; }
                else {
#pragma unroll
                    for (int tt = 0; tt < 4; tt++) acc[i][j][tt] = 0.f;
                }
            }

        for (int c = 0; c < NC; c++) {
            asm volatile("cp.async.wait_group 1;" ::: "memory");
            __syncthreads();

            const uint32_t sb = sbase + (uint32_t)(c % NSTG) * STGB;
            // slice-0 fragments first: start tensor work ASAP
#pragma unroll
            for (int mi = 0; mi < 2; mi++)
                ldsm4(af[0][mi], sb + aoff + mi * 16 * RB);
#pragma unroll
            for (int nt = 0; nt < 4; nt++)
                ldsm4(bf[0][nt], sb + boff + nt * 16 * RB);

            if (c + 2 < NC) {
                const int k0 = (c + 2) * 64;
                const uint32_t off = (uint32_t)((c + 2) % NSTG) * STGB;
#pragma unroll
                for (int i = 0; i < 2; i++) cp16(sAw + off + i * 16, gA + k0 + i * 8);
#pragma unroll
                for (int i = 0; i < 4; i++) cp16(sBw + off + i * 16, gB + k0 + i * 8);
            }
            cp_commit();

#pragma unroll
            for (int ks = 0; ks < 4; ks++) {
                const int cur = ks & 1, nxt = cur ^ 1;
                if (ks < 3) {
                    const uint32_t ko = (uint32_t)(ks + 1) * 32;
#pragma unroll
                    for (int mi = 0; mi < 2; mi++)
                        ldsm4(af[nxt][mi], sb + aoff + mi * 16 * RB + ko);
#pragma unroll
                    for (int nt = 0; nt < 4; nt++)
                        ldsm4(bf[nxt][nt], sb + boff + nt * 16 * RB + ko);
                }
#pragma unroll
                for (int mi = 0; mi < 2; mi++)
#pragma unroll
                    for (int nj = 0; nj < 8; nj++) {
                        if (FACC)
                            mma16816h(hacc[mi][nj], af[cur][mi], &bf[cur][nj >> 1][(nj & 1) * 2]);
                        else
                            mma16816(acc[mi][nj], af[cur][mi], &bf[cur][nj >> 1][(nj & 1) * 2]);
                    }
            }
        }
        __syncthreads();   // all ldsm done before stages 0/1 are rewritten

        const int em0 = m0, en0 = n0;
        const int t2 = t + gridDim.x;
        const bool more = (t2 < ntiles);
        if (more) {
            t = t2;
            m0 = (t / ntn) << 7; n0 = (t % ntn) << 8;
            gA = A + (size_t)(m0 + arow_g) * K + aseg * 16;
            gB = B + (size_t)(n0 + brow_g) * K + bseg * 32;
            // next tile prologue overlaps this tile's epilogue
#pragma unroll
            for (int s = 0; s < NSTG - 1; s++) {
                const int k0 = s * 64;
                const uint32_t off = s * STGB;
#pragma unroll
                for (int i = 0; i < 2; i++) cp16(sAw + off + i * 16, gA + k0 + i * 8);
#pragma unroll
                for (int i = 0; i < 4; i++) cp16(sBw + off + i * 16, gB + k0 + i * 8);
                cp_commit();
            }
        }

        // epilogue for tile (em0, en0)
        const int mrow = em0 + wm * 32 + (lane >> 2);
        const int ncol = en0 + wn * 64 + (lane & 3) * 2;
#pragma unroll
        for (int mi = 0; mi < 2; mi++)
#pragma unroll
            for (int nj = 0; nj < 8; nj++)
#pragma unroll
                for (int hf = 0; hf < 2; hf++) {
                    const int m = mrow + mi * 16 + hf * 8;
                    const int n = ncol + nj * 8;
                    float v0, v1;
                    if (FACC) {
                        const __half2 hv = *reinterpret_cast<__half2*>(&hacc[mi][nj][hf]);
                        const float2 fv = __half22float2(hv);
                        v0 = fv.x; v1 = fv.y;
                    } else {
                        v0 = acc[mi][nj][hf * 2 + 0];
                        v1 = acc[mi][nj][hf * 2 + 1];
                    }
                    if (EPI == 0) {
                        const int mat = n >> 10, hh = (n >> 6) & 15, d = n & 63;
                        const int bb = m >> 11, tq = m & 2047;
                        __half2* dst = reinterpret_cast<__half2*>(
                            Chp + (size_t)mat * (MROWS * EMB) +
                            (((size_t)(bb * HEADS + hh)) * T_SEQ + tq) * HD + d);
                        if (FACC) *dst = *reinterpret_cast<__half2*>(&hacc[mi][nj][hf]);
                        else      *dst = __floats2half2_rn(v0, v1);
                    } else if (EPI == 1) {
                        const size_t base = (size_t)m * N + n;
                        const float2 bs = *reinterpret_cast<const float2*>(bias + n);
                        const float2 rs = *reinterpret_cast<const float2*>(res + base);
                        *reinterpret_cast<float2*>(Cf + base) =
                            make_float2(v0 + bs.x + rs.x, v1 + bs.y + rs.y);
                    } else {
                        const size_t base = (size_t)m * N + n;
                        const float2 bs = *reinterpret_cast<const float2*>(bias + n);
                        *reinterpret_cast<__half2*>(Chp + base) =
                            __floats2half2_rn(fmaxf(v0 + bs.x, 0.f), fmaxf(v1 + bs.y, 0.f));
                    }
                }
        if (!more) break;
    }
}

// -------------------- tensor-core causal flash attention (fp16) -------------
#define KVROWB 144
#define QTILEB  (128 * KVROWB)
#define KVSTGB  (2 * 64 * KVROWB)
#define ATT_SMEM (QTILEB + 2 * KVSTGB)

__global__ void __launch_bounds__(256) attn_mma(
    const __half* __restrict__ Qg, const __half* __restrict__ Kg,
    const __half* __restrict__ Vg, __half* __restrict__ Og)
{
    extern __shared__ char sm[];
    const uint32_t sb = smem_u32(sm);
    const int tid = threadIdx.x, w = tid >> 5, lane = tid & 31;
    const int bh = blockIdx.y;
    const int tileix = (int)gridDim.x - 1 - (int)blockIdx.x;
    const int t0 = tileix * 128;
    const int nc = 2 * tileix + 2;

    const size_t bhbase = (size_t)bh * T_SEQ;

    {
        const int lrow = tid >> 1, lhalf = tid & 1;
        const __half* qs = Qg + (bhbase + t0 + lrow) * HD + lhalf * 32;
        const uint32_t qd = sb + lrow * KVROWB + lhalf * 64;
#pragma unroll
        for (int i = 0; i < 4; i++) cp16(qd + i * 16, qs + i * 8);
    }
    const int krow = tid >> 2, kseg = tid & 3;
    {
        const __half* ks = Kg + (bhbase + krow) * HD + kseg * 16;
        const __half* vs = Vg + (bhbase + krow) * HD + kseg * 16;
        const uint32_t kd = sb + QTILEB + krow * KVROWB + kseg * 32;
        cp16(kd,      ks);
        cp16(kd + 16, ks + 8);
        cp16(kd + 64 * KVROWB,      vs);
        cp16(kd + 64 * KVROWB + 16, vs + 8);
    }
    cp_commit();

    float o[8][4];
#pragma unroll
    for (int dn = 0; dn < 8; dn++)
#pragma unroll
        for (int t = 0; t < 4; t++) o[dn][t] = 0.f;
    float m1 = -1e30f, m2 = -1e30f, l1 = 0.f, l2 = 0.f;
    uint32_t qf[4][4];

    const int arow  = w * 16 + (lane & 15);
    const int akoff = (lane >> 4) * 8;
    const int brow  = (lane & 7) + ((lane >> 4) << 3);
    const int bkoff = ((lane >> 3) & 1) * 8;
    const int vrowo = (lane & 7) + 8 * ((lane >> 3) & 1);
    const int vcolo = 16 * (lane >> 4);
    const int rw = t0 + w * 16;

    for (int c = 0; c < nc; c++) {
        if (c + 1 < nc) {
            const int j0 = (c + 1) * 64;
            const __half* ks = Kg + (bhbase + j0 + krow) * HD + kseg * 16;
            const __half* vs = Vg + (bhbase + j0 + krow) * HD + kseg * 16;
            const uint32_t kd = sb + QTILEB + ((c + 1) & 1) * KVSTGB + krow * KVROWB + kseg * 32;
            cp16(kd,      ks);
            cp16(kd + 16, ks + 8);
            cp16(kd + 64 * KVROWB,      vs);
            cp16(kd + 64 * KVROWB + 16, vs + 8);
            cp_commit();
            asm volatile("cp.async.wait_group 1;" ::: "memory");
        } else {
            asm volatile("cp.async.wait_group 0;" ::: "memory");
        }
        __syncthreads();

        if (c == 0) {
#pragma unroll
            for (int ks = 0; ks < 4; ks++)
                ldsm4(qf[ks], sb + arow * KVROWB + (ks * 16 + akoff) * 2);
        }

        const bool active = (64 * c <= rw + 15);
        const bool diag   = active && (64 * c + 63 > rw);
        if (active) {
            const uint32_t kb = sb + QTILEB + (c & 1) * KVSTGB;
            const uint32_t vb = kb + 64 * KVROWB;

            float s[8][4];
#pragma unroll
            for (int nj = 0; nj < 8; nj++)
#pragma unroll
                for (int t = 0; t < 4; t++) s[nj][t] = 0.f;
#pragma unroll
            for (int ks = 0; ks < 4; ks++) {
                uint32_t bK[4][4];
#pragma unroll
                for (int nt = 0; nt < 4; nt++)
                    ldsm4(bK[nt], kb + (nt * 16 + brow) * KVROWB + (ks * 16 + bkoff) * 2);
#pragma unroll
                for (int nj = 0; nj < 8; nj++)
                    mma16816(s[nj], qf[ks], &bK[nj >> 1][(nj & 1) * 2]);
            }
            const float sc = 0.03125f;
            if (diag) {
                const int r1 = rw + (lane >> 2);
#pragma unroll
                for (int nj = 0; nj < 8; nj++) {
                    const int kvb = 64 * c + nj * 8 + 2 * (lane & 3);
                    s[nj][0] = (kvb     <= r1    ) ? s[nj][0] * sc : -1e30f;
                    s[nj][1] = (kvb + 1 <= r1    ) ? s[nj][1] * sc : -1e30f;
                    s[nj][2] = (kvb     <= r1 + 8) ? s[nj][2] * sc : -1e30f;
                    s[nj][3] = (kvb + 1 <= r1 + 8) ? s[nj][3] * sc : -1e30f;
                }
            } else {
#pragma unroll
                for (int nj = 0; nj < 8; nj++)
#pragma unroll
                    for (int t = 0; t < 4; t++) s[nj][t] *= sc;
            }
            float mx1 = -1e30f, mx2 = -1e30f;
#pragma unroll
            for (int nj = 0; nj < 8; nj++) {
                mx1 = fmaxf(mx1, fmaxf(s[nj][0], s[nj][1]));
                mx2 = fmaxf(mx2, fmaxf(s[nj][2], s[nj][3]));
            }
            mx1 = fmaxf(mx1, __shfl_xor_sync(0xffffffffu, mx1, 1));
            mx1 = fmaxf(mx1, __shfl_xor_sync(0xffffffffu, mx1, 2));
            mx2 = fmaxf(mx2, __shfl_xor_sync(0xffffffffu, mx2, 1));
            mx2 = fmaxf(mx2, __shfl_xor_sync(0xffffffffu, mx2, 2));
            const float nm1 = fmaxf(m1, mx1), nm2 = fmaxf(m2, mx2);
            const float cor1 = __expf(m1 - nm1), cor2 = __expf(m2 - nm2);

            float ps1 = 0.f, ps2 = 0.f;
            uint32_t pf[4][4];
#pragma unroll
            for (int kk = 0; kk < 4; kk++) {
#pragma unroll
                for (int hf = 0; hf < 2; hf++) {
                    const int nj = kk * 2 + hf;
                    const float p0 = __expf(s[nj][0] - nm1);
                    const float p1 = __expf(s[nj][1] - nm1);
                    const float p2 = __expf(s[nj][2] - nm2);
                    const float p3 = __expf(s[nj][3] - nm2);
                    ps1 += p0 + p1;
                    ps2 += p2 + p3;
                    __half2 lo = __floats2half2_rn(p0, p1);
                    __half2 hi = __floats2half2_rn(p2, p3);
                    pf[kk][hf * 2 + 0] = *reinterpret_cast<uint32_t*>(&lo);
                    pf[kk][hf * 2 + 1] = *reinterpret_cast<uint32_t*>(&hi);
                }
            }
            ps1 += __shfl_xor_sync(0xffffffffu, ps1, 1);
            ps1 += __shfl_xor_sync(0xffffffffu, ps1, 2);
            ps2 += __shfl_xor_sync(0xffffffffu, ps2, 1);
            ps2 += __shfl_xor_sync(0xffffffffu, ps2, 2);
            l1 = l1 * cor1 + ps1;
            l2 = l2 * cor2 + ps2;
#pragma unroll
            for (int dn = 0; dn < 8; dn++) {
                o[dn][0] *= cor1; o[dn][1] *= cor1;
                o[dn][2] *= cor2; o[dn][3] *= cor2;
            }
            m1 = nm1; m2 = nm2;

#pragma unroll
            for (int kk = 0; kk < 4; kk++) {
                uint32_t bV[4][4];
                const uint32_t vr = vb + (kk * 16 + vrowo) * KVROWB + vcolo;
#pragma unroll
                for (int d16 = 0; d16 < 4; d16++)
                    ldsm4t(bV[d16], vr + d16 * 32);
#pragma unroll
                for (int dn = 0; dn < 8; dn++)
                    mma16816(o[dn], pf[kk], &bV[dn >> 1][(dn & 1) * 2]);
            }
        }
        __syncthreads();
    }

    const int b = bh >> 4, h = bh & 15;
    const float i1 = 1.f / l1, i2 = 1.f / l2;
    const int r1 = rw + (lane >> 2);
    __half* o1 = Og + ((size_t)(b * T_SEQ) + r1) * EMB + h * HD + 2 * (lane & 3);
    __half* o2 = o1 + (size_t)8 * EMB;
#pragma unroll
    for (int dn = 0; dn < 8; dn++) {
        *reinterpret_cast<__half2*>(o1 + dn * 8) =
            __floats2half2_rn(o[dn][0] * i1, o[dn][1] * i1);
        *reinterpret_cast<__half2*>(o2 + dn * 8) =
            __floats2half2_rn(o[dn][2] * i2, o[dn][3] * i2);
    }
}

// -------------------- launch -------------------------------------------------
static inline int gemm_grid(int M, int N) {
    const int t = (M >> 7) * (N >> 8);
    return t < 148 ? t : 148;
}

extern "C" void kernel_launch(void* const* d_in, const int* in_sizes, int n_in,
                              void* d_out, int out_size)
{
    const float* x   = (const float*)d_in[0];
    const float* wq  = (const float*)d_in[1];
    const float* wk  = (const float*)d_in[2];
    const float* wv  = (const float*)d_in[3];
    const float* wo  = (const float*)d_in[4];
    const float* bo  = (const float*)d_in[5];
    const float* g1  = (const float*)d_in[6];
    const float* b1  = (const float*)d_in[7];
    const float* g2  = (const float*)d_in[8];
    const float* b2  = (const float*)d_in[9];
    const float* w1  = (const float*)d_in[10];
    const float* bf1 = (const float*)d_in[11];
    const float* w2  = (const float*)d_in[12];
    const float* bf2 = (const float*)d_in[13];
    float* out = (float*)d_out;

    cudaFuncSetAttribute(mma_gemm<0,1>, cudaFuncAttributeMaxDynamicSharedMemorySize, GSMEM_BYTES);
    cudaFuncSetAttribute(mma_gemm<1,1>, cudaFuncAttributeMaxDynamicSharedMemorySize, GSMEM_BYTES);
    cudaFuncSetAttribute(mma_gemm<1,0>, cudaFuncAttributeMaxDynamicSharedMemorySize, GSMEM_BYTES);
    cudaFuncSetAttribute(mma_gemm<2,0>, cudaFuncAttributeMaxDynamicSharedMemorySize, GSMEM_BYTES);
    cudaFuncSetAttribute(attn_mma, cudaFuncAttributeMaxDynamicSharedMemorySize, ATT_SMEM);

    __half *h, *qkv, *at, *h2, *u, *wqkvh, *woh, *w1h, *w2h;
    float *x2;
    cudaGetSymbolAddress((void**)&h,     g_h);
    cudaGetSymbolAddress((void**)&qkv,   g_qkv);
    cudaGetSymbolAddress((void**)&at,    g_at);
    cudaGetSymbolAddress((void**)&x2,    g_x2);
    cudaGetSymbolAddress((void**)&h2,    g_h2);
    cudaGetSymbolAddress((void**)&u,     g_u);
    cudaGetSymbolAddress((void**)&wqkvh, g_wqkv);
    cudaGetSymbolAddress((void**)&woh,   g_wo);
    cudaGetSymbolAddress((void**)&w1h,   g_w1);
    cudaGetSymbolAddress((void**)&w2h,   g_w2);

    // 1: fused prep (weight transposes + LN1)
    prep_kernel<<<7168, 256>>>(wq, wk, wv, wo, w1, w2, x, g1, b1,
                               wqkvh, woh, w1h, w2h, h);
    // 2: fused QKV projection (fp16 accumulate, persistent) -> [3][B,H,T,HD]
    mma_gemm<0,1><<<gemm_grid(MROWS, 3 * EMB), 512, GSMEM_BYTES>>>(
        h, wqkvh, nullptr, qkv, nullptr, nullptr, MROWS, 3 * EMB, EMB);
    // 3: tensor-core flash attention (Q-tile 128, big-first) -> fp16 [B,T,C]
    attn_mma<<<dim3(T_SEQ / 128, BATCH * HEADS), 256, ATT_SMEM>>>(
        qkv, qkv + MROWS * EMB, qkv + 2 * MROWS * EMB, at);
    // 4: out projection (fp16 accumulate, persistent) + bias + residual -> x2
    mma_gemm<1,1><<<gemm_grid(MROWS, EMB), 512, GSMEM_BYTES>>>(
        at, woh, x2, nullptr, bo, x, MROWS, EMB, EMB);
    // 5: LN2 -> fp16
    ln_h_kernel<<<MROWS, 256>>>(x2, g2, b2, h2);
    // 6: FFN1 (fp32 accumulate, persistent): relu(h2 @ w1 + bf1) -> fp16
    mma_gemm<2,0><<<gemm_grid(MROWS, FF), 512, GSMEM_BYTES>>>(
        h2, w1h, nullptr, u, bf1, nullptr, MROWS, FF, EMB);
    // 7: FFN2 (fp32 accumulate, persistent): u @ w2 + bf2 + x2 -> out
    mma_gemm<1,0><<<gemm_grid(MROWS, EMB), 512, GSMEM_BYTES>>>(
        u, w2h, out, nullptr, bf2, x2, MROWS, EMB, FF);
}